// round 10
// baseline (speedup 1.0000x reference)
#include <cuda_runtime.h>
#include <cstdint>
#include <cstddef>

// Problem constants
#define K_SEQ    2048
#define K_BATCH  4
#define K_DM     1024
#define K_HEADS  16
#define K_HD     64
#define K_TOK    (K_BATCH * K_SEQ)   // 8192

// Scratch (device globals: allocation-free)
__device__ float g_qkv[(size_t)K_TOK * 3 * K_DM];   // [tok, 3*1024]
__device__ float g_ho [(size_t)K_TOK * K_DM];       // [tok, 1024] head outputs (tf32-rounded)
__device__ float g_xr [(size_t)K_TOK * K_DM];       // tf32-rounded x
__device__ float g_wqr[(size_t)3 * K_DM * K_DM];    // tf32-rounded w_qkv
__device__ float g_wor[(size_t)K_DM * K_DM];        // tf32-rounded w_out

// ---------------------------------------------------------------------------
// helpers
// ---------------------------------------------------------------------------
__device__ __forceinline__ uint32_t f2tf(float f) {
    uint32_t u;
    asm("cvt.rna.tf32.f32 %0, %1;" : "=r"(u) : "f"(f));
    return u;
}

__device__ __forceinline__ void mma_tf32(float* d, const uint32_t* a, const uint32_t* b) {
    asm volatile(
        "mma.sync.aligned.m16n8k8.row.col.f32.tf32.tf32.f32 "
        "{%0,%1,%2,%3}, {%4,%5,%6,%7}, {%8,%9}, {%0,%1,%2,%3};"
        : "+f"(d[0]), "+f"(d[1]), "+f"(d[2]), "+f"(d[3])
        : "r"(a[0]), "r"(a[1]), "r"(a[2]), "r"(a[3]),
          "r"(b[0]), "r"(b[1]));
}

__device__ __forceinline__ uint32_t smem_u32(const void* p) {
    return (uint32_t)__cvta_generic_to_shared(p);
}

__device__ __forceinline__ void cp16(uint32_t dst, const void* src) {
    asm volatile("cp.async.cg.shared.global [%0], [%1], 16;"
                 :: "r"(dst), "l"(src));
}

// ---------------------------------------------------------------------------
// tf32 pre-round: dst[i] = rna_tf32(src[i]) (float4 per thread)
// ---------------------------------------------------------------------------
__global__ __launch_bounds__(256)
void round_tf32(float* __restrict__ dst, const float* __restrict__ src)
{
    size_t i = ((size_t)blockIdx.x * 256 + threadIdx.x) * 4;
    float4 v = *(const float4*)(src + i);
    uint4 t = make_uint4(f2tf(v.x), f2tf(v.y), f2tf(v.z), f2tf(v.w));
    *(uint4*)(dst + i) = t;
}

// ---------------------------------------------------------------------------
// C[M,N] = A[M,K] @ B[N,K]^T + bias[N], tf32 mma.sync.
// v3: inputs are tf32-pre-rounded in gmem (no cvt anywhere in the loop).
// 128x128x32 CTA tile, 128 threads / 4 warps, warp tile 64x64 (1:1 LDS:MMA).
// cp.async double-buffered smem pipeline.
// ---------------------------------------------------------------------------
#define GS 36   // smem row stride in words
#define GEMM_BUF (128 * GS)
#define GEMM_SMEM_BYTES (4 * GEMM_BUF * 4)   // 2 bufs x (A+B)

__global__ __launch_bounds__(128, 2)
void gemm_tf32(const float* __restrict__ A, const float* __restrict__ B,
               const float* __restrict__ bias, float* __restrict__ C,
               int M, int N, int K)
{
    extern __shared__ float gsm[];
    float* As = gsm;                  // [2][128*GS]
    float* Bs = gsm + 2 * GEMM_BUF;   // [2][128*GS]

    const int tid   = threadIdx.x;
    const int lane  = tid & 31;
    const int wid   = tid >> 5;          // 0..3
    const int warpM = (wid >> 1) << 6;   // 0 / 64
    const int warpN = (wid & 1) << 6;    // 0 / 64
    const int m0 = blockIdx.y << 7;
    const int n0 = blockIdx.x << 7;
    const int fr = lane >> 2;            // 0..7
    const int fc = lane & 3;             // 0..3

    float acc[4][8][4];
#pragma unroll
    for (int mi = 0; mi < 4; mi++)
#pragma unroll
        for (int ni = 0; ni < 8; ni++)
#pragma unroll
            for (int r = 0; r < 4; r++) acc[mi][ni][r] = 0.f;

    // Loader: thread tid owns tile row tid (A) / tid (B), 8 x 16B per 32-K chunk
    const float* Ag = A + (size_t)(m0 + tid) * K;
    const float* Bg = B + (size_t)(n0 + tid) * K;
    const uint32_t aBase = smem_u32(As);
    const uint32_t bBase = smem_u32(Bs);
    const uint32_t rowOff = (uint32_t)(tid * GS * 4);

    const int NI = K >> 5;

    // Prefetch iteration 0 into buffer 0
#pragma unroll
    for (int s = 0; s < 8; s++) {
        cp16(aBase + rowOff + s * 16, Ag + s * 4);
        cp16(bBase + rowOff + s * 16, Bg + s * 4);
    }
    asm volatile("cp.async.commit_group;" ::: "memory");

    for (int it = 0; it < NI; it++) {
        const int s = it & 1;

        if (it + 1 < NI) {
            const int k0n = (it + 1) << 5;
            const uint32_t sb = (uint32_t)((s ^ 1) * GEMM_BUF * 4);
#pragma unroll
            for (int p = 0; p < 8; p++) {
                cp16(aBase + sb + rowOff + p * 16, Ag + k0n + p * 4);
                cp16(bBase + sb + rowOff + p * 16, Bg + k0n + p * 4);
            }
            asm volatile("cp.async.commit_group;" ::: "memory");
            asm volatile("cp.async.wait_group 1;" ::: "memory");
        } else {
            asm volatile("cp.async.wait_group 0;" ::: "memory");
        }
        __syncthreads();

        const uint32_t* Asb = (const uint32_t*)(As + s * GEMM_BUF);
        const uint32_t* Bsb = (const uint32_t*)(Bs + s * GEMM_BUF);

#pragma unroll
        for (int ks = 0; ks < 4; ks++) {
            uint32_t a[4][4], b[8][2];
#pragma unroll
            for (int mi = 0; mi < 4; mi++) {
                const uint32_t* p = &Asb[(warpM + mi * 16 + fr) * GS + ks * 8 + fc];
                a[mi][0] = p[0];
                a[mi][1] = p[8 * GS];
                a[mi][2] = p[4];
                a[mi][3] = p[8 * GS + 4];
            }
#pragma unroll
            for (int ni = 0; ni < 8; ni++) {
                const uint32_t* p = &Bsb[(warpN + ni * 8 + fr) * GS + ks * 8 + fc];
                b[ni][0] = p[0];
                b[ni][1] = p[4];
            }
#pragma unroll
            for (int mi = 0; mi < 4; mi++)
#pragma unroll
                for (int ni = 0; ni < 8; ni++)
                    mma_tf32(acc[mi][ni], a[mi], b[ni]);
        }
        __syncthreads();   // all reads of buf s done before it is re-prefetched
    }

    // Epilogue: bias + store
#pragma unroll
    for (int ni = 0; ni < 8; ni++) {
        int c = n0 + warpN + ni * 8 + fc * 2;
        float bb0 = bias[c], bb1 = bias[c + 1];
#pragma unroll
        for (int mi = 0; mi < 4; mi++) {
            int r = m0 + warpM + mi * 16 + fr;
            float2 v0 = make_float2(acc[mi][ni][0] + bb0, acc[mi][ni][1] + bb1);
            float2 v1 = make_float2(acc[mi][ni][2] + bb0, acc[mi][ni][3] + bb1);
            *(float2*)&C[(size_t)r * N + c]       = v0;
            *(float2*)&C[(size_t)(r + 8) * N + c] = v1;
        }
    }
}

// ---------------------------------------------------------------------------
// Tensor-core flash attention (mma.sync, R7 structure). Epilogue rounds ho
// to tf32 so the out-proj GEMM needs no conversion.
// ---------------------------------------------------------------------------
#define AST 68
#define Q_ROWS 128
#define ATTN_SMEM_BYTES ((Q_ROWS + 64 + 64 + Q_ROWS) * AST * 4)
#define VSW(d, j) ((d) * AST + ((j) ^ (((d) & 48) >> 1)))

__global__ __launch_bounds__(256, 2)
void attn_tc(const float* __restrict__ qkv, float* __restrict__ ho)
{
    extern __shared__ uint32_t dsm[];
    uint32_t* Qs = dsm;                        // [128][AST] A-operand layout
    uint32_t* Ks = dsm + Q_ROWS * AST;         // [64][AST]  B-operand layout
    uint32_t* Vt = dsm + (Q_ROWS + 64) * AST;  // [64][AST]  d-major, swizzled
    uint32_t* Ps = dsm + (Q_ROWS + 128) * AST; // [128][AST] A-operand layout

    const int tid  = threadIdx.x;
    const int lane = tid & 31;
    const int wid  = tid >> 5;          // 0..7
    const int wrow = wid << 4;          // 0..112
    const int fr   = lane >> 2;         // 0..7
    const int fc   = lane & 3;          // 0..3

    const int qt = (gridDim.x - 1) - blockIdx.x;   // heavy tiles first
    const int h  = blockIdx.y;
    const int b  = blockIdx.z;
    const int q0 = qt * Q_ROWS;
    const int ktmax = 2 * qt + 1;

    const float* qg = qkv + (size_t)b * K_SEQ * 3 * K_DM + h * K_HD;
    const float* kg = qg + K_DM;
    const float* vg = qg + 2 * K_DM;

    // --- Load Q (pre-scaled by 1/sqrt(d)) into Qs[qrow][d] ---
    {
        const int qr = tid >> 1;            // 0..127
        const int qc = (tid & 1) << 5;      // 0 / 32
        const float* src = qg + (size_t)(q0 + qr) * (3 * K_DM) + qc;
#pragma unroll
        for (int p = 0; p < 32; p += 4) {
            float4 v = *(const float4*)(src + p);
            uint4 t = make_uint4(f2tf(v.x * 0.125f), f2tf(v.y * 0.125f),
                                 f2tf(v.z * 0.125f), f2tf(v.w * 0.125f));
            *(uint4*)&Qs[qr * AST + qc + p] = t;
        }
    }

    // Staging indexing: row = tid>>2 (0..63), col base = (tid&3)*16
    const int lrow = tid >> 2;
    const int lcol = (tid & 3) << 4;

    // Prefetch tile 0 into registers
    float4 stgK[4], stgV[4];
    {
        const float* ks = kg + (size_t)lrow * (3 * K_DM) + lcol;
        const float* vs = vg + (size_t)lrow * (3 * K_DM) + lcol;
#pragma unroll
        for (int p = 0; p < 4; p++) {
            stgK[p] = *(const float4*)(ks + 4 * p);
            stgV[p] = *(const float4*)(vs + 4 * p);
        }
    }

    float o[8][4];
#pragma unroll
    for (int db = 0; db < 8; db++)
#pragma unroll
        for (int r = 0; r < 4; r++) o[db][r] = 0.f;
    float m_i[2] = {-1e30f, -1e30f};
    float l_i[2] = {0.f, 0.f};

    for (int kt = 0; kt <= ktmax; ++kt) {
        const int k0 = kt * 64;
        __syncthreads();

        // Commit staged tile to smem (K row-major tf32, V transposed+swizzled)
#pragma unroll
        for (int p = 0; p < 4; p++) {
            uint4 t = make_uint4(f2tf(stgK[p].x), f2tf(stgK[p].y),
                                 f2tf(stgK[p].z), f2tf(stgK[p].w));
            *(uint4*)&Ks[lrow * AST + lcol + 4 * p] = t;
            const int d0 = lcol + 4 * p;
            Vt[VSW(d0 + 0, lrow)] = f2tf(stgV[p].x);
            Vt[VSW(d0 + 1, lrow)] = f2tf(stgV[p].y);
            Vt[VSW(d0 + 2, lrow)] = f2tf(stgV[p].z);
            Vt[VSW(d0 + 3, lrow)] = f2tf(stgV[p].w);
        }
        __syncthreads();

        const bool active = (k0 <= q0 + wrow + 15);

        if (active) {
            // --- S = (Q/sqrt d) K^T ---
            float s[8][4];
#pragma unroll
            for (int nb = 0; nb < 8; nb++)
#pragma unroll
                for (int r = 0; r < 4; r++) s[nb][r] = 0.f;

#pragma unroll
            for (int ks = 0; ks < 8; ks++) {
                uint32_t a[4];
                const uint32_t* pa = &Qs[(wrow + fr) * AST + ks * 8 + fc];
                a[0] = pa[0];
                a[1] = pa[8 * AST];
                a[2] = pa[4];
                a[3] = pa[8 * AST + 4];
#pragma unroll
                for (int nb = 0; nb < 8; nb++) {
                    uint32_t bfr[2];
                    const uint32_t* pb = &Ks[(nb * 8 + fr) * AST + ks * 8 + fc];
                    bfr[0] = pb[0];
                    bfr[1] = pb[4];
                    mma_tf32(s[nb], a, bfr);
                }
            }

            // Causal mask (only when tile straddles this warp's diagonal)
            if (k0 + 63 > q0 + wrow) {
#pragma unroll
                for (int nb = 0; nb < 8; nb++) {
                    int c0 = k0 + nb * 8 + 2 * fc;
#pragma unroll
                    for (int rh = 0; rh < 2; rh++) {
                        int row = q0 + wrow + fr + rh * 8;
                        if (c0 > row)     s[nb][rh * 2 + 0] = -1e30f;
                        if (c0 + 1 > row) s[nb][rh * 2 + 1] = -1e30f;
                    }
                }
            }

            // --- Online softmax ---
#pragma unroll
            for (int rh = 0; rh < 2; rh++) {
                float mr = -1e30f;
#pragma unroll
                for (int nb = 0; nb < 8; nb++)
                    mr = fmaxf(mr, fmaxf(s[nb][rh * 2], s[nb][rh * 2 + 1]));
                mr = fmaxf(mr, __shfl_xor_sync(0xffffffffu, mr, 1));
                mr = fmaxf(mr, __shfl_xor_sync(0xffffffffu, mr, 2));
                float mnew  = fmaxf(m_i[rh], mr);
                float alpha = __expf(m_i[rh] - mnew);
                float rs = 0.f;
#pragma unroll
                for (int nb = 0; nb < 8; nb++) {
                    float e0 = __expf(s[nb][rh * 2]     - mnew);
                    float e1 = __expf(s[nb][rh * 2 + 1] - mnew);
                    s[nb][rh * 2]     = e0;
                    s[nb][rh * 2 + 1] = e1;
                    rs += e0 + e1;
                }
                rs += __shfl_xor_sync(0xffffffffu, rs, 1);
                rs += __shfl_xor_sync(0xffffffffu, rs, 2);
                l_i[rh] = l_i[rh] * alpha + rs;
                m_i[rh] = mnew;
#pragma unroll
                for (int db = 0; db < 8; db++) {
                    o[db][rh * 2]     *= alpha;
                    o[db][rh * 2 + 1] *= alpha;
                }
            }

            // --- Re-fragment P via per-warp smem rows ---
#pragma unroll
            for (int nb = 0; nb < 8; nb++) {
                uint2 v0 = make_uint2(f2tf(s[nb][0]), f2tf(s[nb][1]));
                uint2 v1 = make_uint2(f2tf(s[nb][2]), f2tf(s[nb][3]));
                *(uint2*)&Ps[(wrow + fr)     * AST + nb * 8 + 2 * fc] = v0;
                *(uint2*)&Ps[(wrow + fr + 8) * AST + nb * 8 + 2 * fc] = v1;
            }
            __syncwarp();
        }

        // Prefetch next K/V tile while PV math runs (hides L2 latency)
        if (kt < ktmax) {
            const int kn = (kt + 1) * 64;
            const float* ks = kg + (size_t)(kn + lrow) * (3 * K_DM) + lcol;
            const float* vs = vg + (size_t)(kn + lrow) * (3 * K_DM) + lcol;
#pragma unroll
            for (int p = 0; p < 4; p++) {
                stgK[p] = *(const float4*)(ks + 4 * p);
                stgV[p] = *(const float4*)(vs + 4 * p);
            }
        }

        if (active) {
            // --- O += P @ V ---
#pragma unroll
            for (int ks = 0; ks < 8; ks++) {
                uint32_t a[4];
                const uint32_t* pa = &Ps[(wrow + fr) * AST + ks * 8 + fc];
                a[0] = pa[0];
                a[1] = pa[8 * AST];
                a[2] = pa[4];
                a[3] = pa[8 * AST + 4];
#pragma unroll
                for (int db = 0; db < 8; db++) {
                    uint32_t bfr[2];
                    const uint32_t* pb = &Vt[VSW(db * 8 + fr, ks * 8 + fc)];
                    bfr[0] = pb[0];
                    bfr[1] = pb[4];
                    mma_tf32(o[db], a, bfr);
                }
            }
            __syncwarp();
        }
    }

    // Epilogue: normalize, round to tf32 (out-proj input), write [tok, h*64+d]
    float inv0 = 1.f / l_i[0];
    float inv1 = 1.f / l_i[1];
#pragma unroll
    for (int db = 0; db < 8; db++) {
        size_t r0 = (size_t)b * K_SEQ + q0 + wrow + fr;
        int c = h * K_HD + db * 8 + 2 * fc;
        *(float2*)&ho[r0 * K_DM + c] =
            make_float2(__uint_as_float(f2tf(o[db][0] * inv0)),
                        __uint_as_float(f2tf(o[db][1] * inv0)));
        *(float2*)&ho[(r0 + 8) * K_DM + c] =
            make_float2(__uint_as_float(f2tf(o[db][2] * inv1)),
                        __uint_as_float(f2tf(o[db][3] * inv1)));
    }
}

// ---------------------------------------------------------------------------
extern "C" void kernel_launch(void* const* d_in, const int* in_sizes, int n_in,
                              void* d_out, int out_size)
{
    const float* x     = (const float*)d_in[0];
    const float* w_qkv = (const float*)d_in[1];
    const float* b_qkv = (const float*)d_in[2];
    const float* w_out = (const float*)d_in[3];
    const float* b_out = (const float*)d_in[4];
    float* out = (float*)d_out;

    float *qkv, *ho, *xr, *wqr, *wor;
    cudaGetSymbolAddress((void**)&qkv, g_qkv);
    cudaGetSymbolAddress((void**)&ho,  g_ho);
    cudaGetSymbolAddress((void**)&xr,  g_xr);
    cudaGetSymbolAddress((void**)&wqr, g_wqr);
    cudaGetSymbolAddress((void**)&wor, g_wor);
    cudaFuncSetAttribute(gemm_tf32,
                         cudaFuncAttributeMaxDynamicSharedMemorySize,
                         GEMM_SMEM_BYTES);
    cudaFuncSetAttribute(attn_tc,
                         cudaFuncAttributeMaxDynamicSharedMemorySize,
                         ATTN_SMEM_BYTES);

    // 0) pre-round GEMM inputs to tf32 (rna): smem bits become exact tf32
    round_tf32<<<(K_TOK * K_DM) / 1024, 256>>>(xr, x);
    round_tf32<<<(3 * K_DM * K_DM) / 1024, 256>>>(wqr, w_qkv);
    round_tf32<<<(K_DM * K_DM) / 1024, 256>>>(wor, w_out);

    // 1) qkv = x @ w_qkv^T + b_qkv     [8192, 3072]
    gemm_tf32<<<dim3((3 * K_DM) / 128, K_TOK / 128), 128, GEMM_SMEM_BYTES>>>(
        xr, wqr, b_qkv, qkv, K_TOK, 3 * K_DM, K_DM);

    // 2) causal flash attention (mma.sync) -> [8192, 1024]
    attn_tc<<<dim3(K_SEQ / Q_ROWS, K_HEADS, K_BATCH), 256, ATTN_SMEM_BYTES>>>(
        qkv, ho);

    // 3) out = ho @ w_out^T + b_out    [8192, 1024]
    gemm_tf32<<<dim3(K_DM / 128, K_TOK / 128), 128, GEMM_SMEM_BYTES>>>(
        ho, wor, b_out, out, K_TOK, K_DM, K_DM);
}

// round 12
// speedup vs baseline: 1.1352x; 1.1352x over previous
#include <cuda_runtime.h>
#include <cstdint>
#include <cstddef>

// Problem constants
#define K_SEQ    2048
#define K_BATCH  4
#define K_DM     1024
#define K_HEADS  16
#define K_HD     64
#define K_TOK    (K_BATCH * K_SEQ)   // 8192

// Scratch (device globals: allocation-free)
__device__ float g_qkv[(size_t)K_TOK * 3 * K_DM];   // [tok, 3*1024]
__device__ float g_ho [(size_t)K_TOK * K_DM];       // [tok, 1024] head outputs (tf32-rounded)
__device__ float g_xr [(size_t)K_TOK * K_DM];       // tf32-rounded x
__device__ float g_wqr[(size_t)3 * K_DM * K_DM];    // tf32-rounded w_qkv
__device__ float g_wor[(size_t)K_DM * K_DM];        // tf32-rounded w_out

// ---------------------------------------------------------------------------
// helpers
// ---------------------------------------------------------------------------
__device__ __forceinline__ uint32_t f2tf(float f) {
    uint32_t u;
    asm("cvt.rna.tf32.f32 %0, %1;" : "=r"(u) : "f"(f));
    return u;
}

__device__ __forceinline__ void mma_tf32(float* d, const uint32_t* a, const uint32_t* b) {
    asm volatile(
        "mma.sync.aligned.m16n8k8.row.col.f32.tf32.tf32.f32 "
        "{%0,%1,%2,%3}, {%4,%5,%6,%7}, {%8,%9}, {%0,%1,%2,%3};"
        : "+f"(d[0]), "+f"(d[1]), "+f"(d[2]), "+f"(d[3])
        : "r"(a[0]), "r"(a[1]), "r"(a[2]), "r"(a[3]),
          "r"(b[0]), "r"(b[1]));
}

__device__ __forceinline__ uint32_t smem_u32(const void* p) {
    return (uint32_t)__cvta_generic_to_shared(p);
}

__device__ __forceinline__ void cp16(uint32_t dst, const void* src) {
    asm volatile("cp.async.cg.shared.global [%0], [%1], 16;"
                 :: "r"(dst), "l"(src));
}

// ---------------------------------------------------------------------------
// tf32 pre-round: dst[i] = rna_tf32(src[i]) (float4 per thread)
// ---------------------------------------------------------------------------
__global__ __launch_bounds__(256)
void round_tf32(float* __restrict__ dst, const float* __restrict__ src)
{
    size_t i = ((size_t)blockIdx.x * 256 + threadIdx.x) * 4;
    float4 v = *(const float4*)(src + i);
    uint4 t = make_uint4(f2tf(v.x), f2tf(v.y), f2tf(v.z), f2tf(v.w));
    *(uint4*)(dst + i) = t;
}

// ---------------------------------------------------------------------------
// C[M,N] = A[M,K] @ B[N,K]^T + bias[N], tf32 mma.sync.
// R8 structure (128x128x32 CTA, 256 thr, 8 warps of 64x32, cp.async double
// buffer, 2 CTAs/SM), NO cvt in the loop (inputs pre-rounded to tf32).
// Loader: 2 threads per tile row, each copies 4 contiguous 16B segments
// (even thread bytes [0,64), odd thread bytes [64,128) of the 128B chunk).
// ---------------------------------------------------------------------------
#define GS 36   // smem row stride in words
#define GEMM_BUF (128 * GS)
#define GEMM_SMEM_BYTES (4 * GEMM_BUF * 4)   // 2 bufs x (A+B)

__global__ __launch_bounds__(256, 2)
void gemm_tf32(const float* __restrict__ A, const float* __restrict__ B,
               const float* __restrict__ bias, float* __restrict__ C,
               int M, int N, int K)
{
    extern __shared__ float gsm[];
    float* As = gsm;                  // [2][128*GS]
    float* Bs = gsm + 2 * GEMM_BUF;   // [2][128*GS]

    const int tid   = threadIdx.x;
    const int lane  = tid & 31;
    const int wid   = tid >> 5;
    const int warpM = (wid >> 2) << 6;   // 0 / 64
    const int warpN = (wid & 3) << 5;    // 0 / 32 / 64 / 96
    const int m0 = blockIdx.y << 7;
    const int n0 = blockIdx.x << 7;
    const int fr = lane >> 2;            // 0..7
    const int fc = lane & 3;             // 0..3

    float acc[4][4][4];
#pragma unroll
    for (int mi = 0; mi < 4; mi++)
#pragma unroll
        for (int ni = 0; ni < 4; ni++)
#pragma unroll
            for (int r = 0; r < 4; r++) acc[mi][ni][r] = 0.f;

    const int grow = tid >> 1;           // 0..127 tile row
    const int ghf  = (tid & 1) * 16;     // float offset within 32-float chunk

    const float* Ag = A + (size_t)(m0 + grow) * K + ghf;
    const float* Bg = B + (size_t)(n0 + grow) * K + ghf;
    const uint32_t aBase = smem_u32(As);
    const uint32_t bBase = smem_u32(Bs);
    const uint32_t rowOff = (uint32_t)((grow * GS + ghf) * 4);

    const int NI = K >> 5;

    // Prefetch iteration 0 into buffer 0 (each thread: 4x16B A + 4x16B B)
#pragma unroll
    for (int s = 0; s < 4; s++) {
        cp16(aBase + rowOff + s * 16, Ag + s * 4);
        cp16(bBase + rowOff + s * 16, Bg + s * 4);
    }
    asm volatile("cp.async.commit_group;" ::: "memory");

    for (int it = 0; it < NI; it++) {
        const int s = it & 1;

        if (it + 1 < NI) {
            const int k0n = (it + 1) << 5;
            const uint32_t sb = (uint32_t)((s ^ 1) * GEMM_BUF * 4);
#pragma unroll
            for (int p = 0; p < 4; p++) {
                cp16(aBase + sb + rowOff + p * 16, Ag + k0n + p * 4);
                cp16(bBase + sb + rowOff + p * 16, Bg + k0n + p * 4);
            }
            asm volatile("cp.async.commit_group;" ::: "memory");
            asm volatile("cp.async.wait_group 1;" ::: "memory");
        } else {
            asm volatile("cp.async.wait_group 0;" ::: "memory");
        }
        __syncthreads();

        const uint32_t* Asb = (const uint32_t*)(As + s * GEMM_BUF);
        const uint32_t* Bsb = (const uint32_t*)(Bs + s * GEMM_BUF);

#pragma unroll
        for (int ks = 0; ks < 4; ks++) {
            uint32_t a[4][4], b[4][2];
#pragma unroll
            for (int mi = 0; mi < 4; mi++) {
                const uint32_t* p = &Asb[(warpM + mi * 16 + fr) * GS + ks * 8 + fc];
                a[mi][0] = p[0];
                a[mi][1] = p[8 * GS];
                a[mi][2] = p[4];
                a[mi][3] = p[8 * GS + 4];
            }
#pragma unroll
            for (int ni = 0; ni < 4; ni++) {
                const uint32_t* p = &Bsb[(warpN + ni * 8 + fr) * GS + ks * 8 + fc];
                b[ni][0] = p[0];
                b[ni][1] = p[4];
            }
#pragma unroll
            for (int mi = 0; mi < 4; mi++)
#pragma unroll
                for (int ni = 0; ni < 4; ni++)
                    mma_tf32(acc[mi][ni], a[mi], b[ni]);
        }
        __syncthreads();   // all reads of buf s done before it is re-prefetched
    }

    // Epilogue: bias + store
#pragma unroll
    for (int ni = 0; ni < 4; ni++) {
        int c = n0 + warpN + ni * 8 + fc * 2;
        float bb0 = bias[c], bb1 = bias[c + 1];
#pragma unroll
        for (int mi = 0; mi < 4; mi++) {
            int r = m0 + warpM + mi * 16 + fr;
            float2 v0 = make_float2(acc[mi][ni][0] + bb0, acc[mi][ni][1] + bb1);
            float2 v1 = make_float2(acc[mi][ni][2] + bb0, acc[mi][ni][3] + bb1);
            *(float2*)&C[(size_t)r * N + c]       = v0;
            *(float2*)&C[(size_t)(r + 8) * N + c] = v1;
        }
    }
}

// ---------------------------------------------------------------------------
// Tensor-core flash attention (mma.sync, R7 structure). Epilogue rounds ho
// to tf32 so the out-proj GEMM needs no conversion.
// ---------------------------------------------------------------------------
#define AST 68
#define Q_ROWS 128
#define ATTN_SMEM_BYTES ((Q_ROWS + 64 + 64 + Q_ROWS) * AST * 4)
#define VSW(d, j) ((d) * AST + ((j) ^ (((d) & 48) >> 1)))

__global__ __launch_bounds__(256, 2)
void attn_tc(const float* __restrict__ qkv, float* __restrict__ ho)
{
    extern __shared__ uint32_t dsm[];
    uint32_t* Qs = dsm;                        // [128][AST] A-operand layout
    uint32_t* Ks = dsm + Q_ROWS * AST;         // [64][AST]  B-operand layout
    uint32_t* Vt = dsm + (Q_ROWS + 64) * AST;  // [64][AST]  d-major, swizzled
    uint32_t* Ps = dsm + (Q_ROWS + 128) * AST; // [128][AST] A-operand layout

    const int tid  = threadIdx.x;
    const int lane = tid & 31;
    const int wid  = tid >> 5;          // 0..7
    const int wrow = wid << 4;          // 0..112
    const int fr   = lane >> 2;         // 0..7
    const int fc   = lane & 3;          // 0..3

    const int qt = (gridDim.x - 1) - blockIdx.x;   // heavy tiles first
    const int h  = blockIdx.y;
    const int b  = blockIdx.z;
    const int q0 = qt * Q_ROWS;
    const int ktmax = 2 * qt + 1;

    const float* qg = qkv + (size_t)b * K_SEQ * 3 * K_DM + h * K_HD;
    const float* kg = qg + K_DM;
    const float* vg = qg + 2 * K_DM;

    // --- Load Q (pre-scaled by 1/sqrt(d)) into Qs[qrow][d] ---
    {
        const int qr = tid >> 1;            // 0..127
        const int qc = (tid & 1) << 5;      // 0 / 32
        const float* src = qg + (size_t)(q0 + qr) * (3 * K_DM) + qc;
#pragma unroll
        for (int p = 0; p < 32; p += 4) {
            float4 v = *(const float4*)(src + p);
            uint4 t = make_uint4(f2tf(v.x * 0.125f), f2tf(v.y * 0.125f),
                                 f2tf(v.z * 0.125f), f2tf(v.w * 0.125f));
            *(uint4*)&Qs[qr * AST + qc + p] = t;
        }
    }

    // Staging indexing: row = tid>>2 (0..63), col base = (tid&3)*16
    const int lrow = tid >> 2;
    const int lcol = (tid & 3) << 4;

    // Prefetch tile 0 into registers
    float4 stgK[4], stgV[4];
    {
        const float* ks = kg + (size_t)lrow * (3 * K_DM) + lcol;
        const float* vs = vg + (size_t)lrow * (3 * K_DM) + lcol;
#pragma unroll
        for (int p = 0; p < 4; p++) {
            stgK[p] = *(const float4*)(ks + 4 * p);
            stgV[p] = *(const float4*)(vs + 4 * p);
        }
    }

    float o[8][4];
#pragma unroll
    for (int db = 0; db < 8; db++)
#pragma unroll
        for (int r = 0; r < 4; r++) o[db][r] = 0.f;
    float m_i[2] = {-1e30f, -1e30f};
    float l_i[2] = {0.f, 0.f};

    for (int kt = 0; kt <= ktmax; ++kt) {
        const int k0 = kt * 64;
        __syncthreads();

        // Commit staged tile to smem (K row-major tf32, V transposed+swizzled)
#pragma unroll
        for (int p = 0; p < 4; p++) {
            uint4 t = make_uint4(f2tf(stgK[p].x), f2tf(stgK[p].y),
                                 f2tf(stgK[p].z), f2tf(stgK[p].w));
            *(uint4*)&Ks[lrow * AST + lcol + 4 * p] = t;
            const int d0 = lcol + 4 * p;
            Vt[VSW(d0 + 0, lrow)] = f2tf(stgV[p].x);
            Vt[VSW(d0 + 1, lrow)] = f2tf(stgV[p].y);
            Vt[VSW(d0 + 2, lrow)] = f2tf(stgV[p].z);
            Vt[VSW(d0 + 3, lrow)] = f2tf(stgV[p].w);
        }
        __syncthreads();

        const bool active = (k0 <= q0 + wrow + 15);

        if (active) {
            // --- S = (Q/sqrt d) K^T ---
            float s[8][4];
#pragma unroll
            for (int nb = 0; nb < 8; nb++)
#pragma unroll
                for (int r = 0; r < 4; r++) s[nb][r] = 0.f;

#pragma unroll
            for (int ks = 0; ks < 8; ks++) {
                uint32_t a[4];
                const uint32_t* pa = &Qs[(wrow + fr) * AST + ks * 8 + fc];
                a[0] = pa[0];
                a[1] = pa[8 * AST];
                a[2] = pa[4];
                a[3] = pa[8 * AST + 4];
#pragma unroll
                for (int nb = 0; nb < 8; nb++) {
                    uint32_t bfr[2];
                    const uint32_t* pb = &Ks[(nb * 8 + fr) * AST + ks * 8 + fc];
                    bfr[0] = pb[0];
                    bfr[1] = pb[4];
                    mma_tf32(s[nb], a, bfr);
                }
            }

            // Causal mask (only when tile straddles this warp's diagonal)
            if (k0 + 63 > q0 + wrow) {
#pragma unroll
                for (int nb = 0; nb < 8; nb++) {
                    int c0 = k0 + nb * 8 + 2 * fc;
#pragma unroll
                    for (int rh = 0; rh < 2; rh++) {
                        int row = q0 + wrow + fr + rh * 8;
                        if (c0 > row)     s[nb][rh * 2 + 0] = -1e30f;
                        if (c0 + 1 > row) s[nb][rh * 2 + 1] = -1e30f;
                    }
                }
            }

            // --- Online softmax ---
#pragma unroll
            for (int rh = 0; rh < 2; rh++) {
                float mr = -1e30f;
#pragma unroll
                for (int nb = 0; nb < 8; nb++)
                    mr = fmaxf(mr, fmaxf(s[nb][rh * 2], s[nb][rh * 2 + 1]));
                mr = fmaxf(mr, __shfl_xor_sync(0xffffffffu, mr, 1));
                mr = fmaxf(mr, __shfl_xor_sync(0xffffffffu, mr, 2));
                float mnew  = fmaxf(m_i[rh], mr);
                float alpha = __expf(m_i[rh] - mnew);
                float rs = 0.f;
#pragma unroll
                for (int nb = 0; nb < 8; nb++) {
                    float e0 = __expf(s[nb][rh * 2]     - mnew);
                    float e1 = __expf(s[nb][rh * 2 + 1] - mnew);
                    s[nb][rh * 2]     = e0;
                    s[nb][rh * 2 + 1] = e1;
                    rs += e0 + e1;
                }
                rs += __shfl_xor_sync(0xffffffffu, rs, 1);
                rs += __shfl_xor_sync(0xffffffffu, rs, 2);
                l_i[rh] = l_i[rh] * alpha + rs;
                m_i[rh] = mnew;
#pragma unroll
                for (int db = 0; db < 8; db++) {
                    o[db][rh * 2]     *= alpha;
                    o[db][rh * 2 + 1] *= alpha;
                }
            }

            // --- Re-fragment P via per-warp smem rows ---
#pragma unroll
            for (int nb = 0; nb < 8; nb++) {
                uint2 v0 = make_uint2(f2tf(s[nb][0]), f2tf(s[nb][1]));
                uint2 v1 = make_uint2(f2tf(s[nb][2]), f2tf(s[nb][3]));
                *(uint2*)&Ps[(wrow + fr)     * AST + nb * 8 + 2 * fc] = v0;
                *(uint2*)&Ps[(wrow + fr + 8) * AST + nb * 8 + 2 * fc] = v1;
            }
            __syncwarp();
        }

        // Prefetch next K/V tile while PV math runs (hides L2 latency)
        if (kt < ktmax) {
            const int kn = (kt + 1) * 64;
            const float* ks = kg + (size_t)(kn + lrow) * (3 * K_DM) + lcol;
            const float* vs = vg + (size_t)(kn + lrow) * (3 * K_DM) + lcol;
#pragma unroll
            for (int p = 0; p < 4; p++) {
                stgK[p] = *(const float4*)(ks + 4 * p);
                stgV[p] = *(const float4*)(vs + 4 * p);
            }
        }

        if (active) {
            // --- O += P @ V ---
#pragma unroll
            for (int ks = 0; ks < 8; ks++) {
                uint32_t a[4];
                const uint32_t* pa = &Ps[(wrow + fr) * AST + ks * 8 + fc];
                a[0] = pa[0];
                a[1] = pa[8 * AST];
                a[2] = pa[4];
                a[3] = pa[8 * AST + 4];
#pragma unroll
                for (int db = 0; db < 8; db++) {
                    uint32_t bfr[2];
                    const uint32_t* pb = &Vt[VSW(db * 8 + fr, ks * 8 + fc)];
                    bfr[0] = pb[0];
                    bfr[1] = pb[4];
                    mma_tf32(o[db], a, bfr);
                }
            }
            __syncwarp();
        }
    }

    // Epilogue: normalize, round to tf32 (out-proj input), write [tok, h*64+d]
    float inv0 = 1.f / l_i[0];
    float inv1 = 1.f / l_i[1];
#pragma unroll
    for (int db = 0; db < 8; db++) {
        size_t r0 = (size_t)b * K_SEQ + q0 + wrow + fr;
        int c = h * K_HD + db * 8 + 2 * fc;
        *(float2*)&ho[r0 * K_DM + c] =
            make_float2(__uint_as_float(f2tf(o[db][0] * inv0)),
                        __uint_as_float(f2tf(o[db][1] * inv0)));
        *(float2*)&ho[(r0 + 8) * K_DM + c] =
            make_float2(__uint_as_float(f2tf(o[db][2] * inv1)),
                        __uint_as_float(f2tf(o[db][3] * inv1)));
    }
}

// ---------------------------------------------------------------------------
extern "C" void kernel_launch(void* const* d_in, const int* in_sizes, int n_in,
                              void* d_out, int out_size)
{
    const float* x     = (const float*)d_in[0];
    const float* w_qkv = (const float*)d_in[1];
    const float* b_qkv = (const float*)d_in[2];
    const float* w_out = (const float*)d_in[3];
    const float* b_out = (const float*)d_in[4];
    float* out = (float*)d_out;

    float *qkv, *ho, *xr, *wqr, *wor;
    cudaGetSymbolAddress((void**)&qkv, g_qkv);
    cudaGetSymbolAddress((void**)&ho,  g_ho);
    cudaGetSymbolAddress((void**)&xr,  g_xr);
    cudaGetSymbolAddress((void**)&wqr, g_wqr);
    cudaGetSymbolAddress((void**)&wor, g_wor);
    cudaFuncSetAttribute(gemm_tf32,
                         cudaFuncAttributeMaxDynamicSharedMemorySize,
                         GEMM_SMEM_BYTES);
    cudaFuncSetAttribute(attn_tc,
                         cudaFuncAttributeMaxDynamicSharedMemorySize,
                         ATTN_SMEM_BYTES);

    // 0) pre-round GEMM inputs to tf32 (rna): smem bits become exact tf32
    round_tf32<<<(K_TOK * K_DM) / 1024, 256>>>(xr, x);
    round_tf32<<<(3 * K_DM * K_DM) / 1024, 256>>>(wqr, w_qkv);
    round_tf32<<<(K_DM * K_DM) / 1024, 256>>>(wor, w_out);

    // 1) qkv = x @ w_qkv^T + b_qkv     [8192, 3072]
    gemm_tf32<<<dim3((3 * K_DM) / 128, K_TOK / 128), 256, GEMM_SMEM_BYTES>>>(
        xr, wqr, b_qkv, qkv, K_TOK, 3 * K_DM, K_DM);

    // 2) causal flash attention (mma.sync) -> [8192, 1024]
    attn_tc<<<dim3(K_SEQ / Q_ROWS, K_HEADS, K_BATCH), 256, ATTN_SMEM_BYTES>>>(
        qkv, ho);

    // 3) out = ho @ w_out^T + b_out    [8192, 1024]
    gemm_tf32<<<dim3(K_DM / 128, K_TOK / 128), 256, GEMM_SMEM_BYTES>>>(
        ho, wor, b_out, out, K_TOK, K_DM, K_DM);
}